// round 1
// baseline (speedup 1.0000x reference)
#include <cuda_runtime.h>

#define S_LEN 2048
#define D_DIM 1024
#define BATCH 4

// Scratch (allocation-free rule: __device__ globals)
__device__ float g_Q [(size_t)BATCH * S_LEN * D_DIM];
__device__ float g_K [(size_t)BATCH * S_LEN * D_DIM];
__device__ float g_V [(size_t)BATCH * S_LEN * D_DIM];
__device__ float g_Sc[(size_t)BATCH * S_LEN * S_LEN];

// ---- packed f32x2 helpers (B300: 2x fp32 FMA throughput vs scalar FFMA) ----
__device__ __forceinline__ unsigned long long pk2(float x, float y) {
    unsigned long long r;
    asm("mov.b64 %0, {%1, %2};" : "=l"(r) : "f"(x), "f"(y));
    return r;
}
__device__ __forceinline__ unsigned long long f2fma(unsigned long long a,
                                                    unsigned long long b,
                                                    unsigned long long c) {
    unsigned long long d;
    asm("fma.rn.f32x2 %0, %1, %2, %3;" : "=l"(d) : "l"(a), "l"(b), "l"(c));
    return d;
}
__device__ __forceinline__ float2 upk2(unsigned long long v) {
    float2 r;
    asm("mov.b64 {%0, %1}, %2;" : "=f"(r.x), "=f"(r.y) : "l"(v));
    return r;
}

// ============================================================================
// 128x128x16 fp32 GEMM, 256 threads, 8x8 per thread (packed 8x4 f32x2).
// TB=false: C[M,N] = A[M,K] (row-major) * B[K,N] (row-major)
// TB=true : C[M,N] = A[M,K] * B[N,K]^T
// blockIdx.z batches via sA/sB/sC element strides.
// All of M,N divisible by 128; K divisible by 16 (guaranteed by shapes).
// ============================================================================
template <bool TB>
__global__ void __launch_bounds__(256, 2)
gemm128(const float* __restrict__ Ag, const float* __restrict__ Bg,
        float* __restrict__ Cg, int M, int N, int K,
        long sA, long sB, long sC)
{
    constexpr int BM = 128, BN = 128, BK = 16, LDSH = 132;  // +4 pad: 16B-aligned rows, fewer STS conflicts
    __shared__ float As[BK][LDSH];
    __shared__ float Bs[BK][LDSH];

    const float* A = Ag + (long)blockIdx.z * sA;
    const float* B = Bg + (long)blockIdx.z * sB;
    float*       C = Cg + (long)blockIdx.z * sC;

    const int bm = blockIdx.y * BM;
    const int bn = blockIdx.x * BN;

    const int tid  = threadIdx.x;
    const int lane = tid & 31;
    const int warp = tid >> 5;
    // warps 4(m) x 2(n); lanes 4(m) x 8(n) -> 32x64 per warp, 8x8 per thread
    const int tm0 = (warp >> 1) * 32 + (lane & 3) * 8;
    const int tn0 = (warp & 1) * 64 + (lane >> 2) * 8;

    // tile-load indices
    const int ar = tid >> 2;        // 0..63 (row in 128x16 tile, +64 for 2nd half)
    const int ac = (tid & 3) << 2;  // 0,4,8,12
    const int br = tid >> 5;        // 0..7 (row in 16x128 tile, +8 for 2nd half)
    const int bc = (tid & 31) << 2; // 0..124

    const float* Ap0 = A + (long)(bm + ar) * K + ac;
    const float* Ap1 = Ap0 + (long)64 * K;
    const float* Bp0;
    const float* Bp1;
    if (TB) { Bp0 = B + (long)(bn + ar) * K + ac; Bp1 = Bp0 + (long)64 * K; }
    else    { Bp0 = B + (long)br * N + bn + bc;   Bp1 = Bp0 + (long)8 * N;  }

    unsigned long long acc[8][4];
#pragma unroll
    for (int i = 0; i < 8; i++)
#pragma unroll
        for (int j = 0; j < 4; j++) acc[i][j] = 0ull;

    // stage first tile in registers
    float4 pa0 = *(const float4*)Ap0;
    float4 pa1 = *(const float4*)Ap1;
    float4 pb0 = *(const float4*)Bp0;
    float4 pb1 = *(const float4*)Bp1;

    const int nk = K / BK;
    for (int t = 0; t < nk; ++t) {
        // commit staged tile to smem (A and NT-B transposed: As[k][m])
        As[ac + 0][ar] = pa0.x; As[ac + 1][ar] = pa0.y;
        As[ac + 2][ar] = pa0.z; As[ac + 3][ar] = pa0.w;
        As[ac + 0][ar + 64] = pa1.x; As[ac + 1][ar + 64] = pa1.y;
        As[ac + 2][ar + 64] = pa1.z; As[ac + 3][ar + 64] = pa1.w;
        if (TB) {
            Bs[ac + 0][ar] = pb0.x; Bs[ac + 1][ar] = pb0.y;
            Bs[ac + 2][ar] = pb0.z; Bs[ac + 3][ar] = pb0.w;
            Bs[ac + 0][ar + 64] = pb1.x; Bs[ac + 1][ar + 64] = pb1.y;
            Bs[ac + 2][ar + 64] = pb1.z; Bs[ac + 3][ar + 64] = pb1.w;
        } else {
            *(float4*)&Bs[br][bc]     = pb0;
            *(float4*)&Bs[br + 8][bc] = pb1;
        }
        __syncthreads();

        // prefetch next global tile into registers (hidden under compute)
        if (t + 1 < nk) {
            const int off = (t + 1) * BK;
            pa0 = *(const float4*)(Ap0 + off);
            pa1 = *(const float4*)(Ap1 + off);
            if (TB) {
                pb0 = *(const float4*)(Bp0 + off);
                pb1 = *(const float4*)(Bp1 + off);
            } else {
                pb0 = *(const float4*)(Bp0 + (long)off * N);
                pb1 = *(const float4*)(Bp1 + (long)off * N);
            }
        }

#pragma unroll
        for (int kk = 0; kk < BK; ++kk) {
            float a[8];
            *(float4*)(a)     = *(const float4*)&As[kk][tm0];
            *(float4*)(a + 4) = *(const float4*)&As[kk][tm0 + 4];
            float4 bb0 = *(const float4*)&Bs[kk][tn0];
            float4 bb1 = *(const float4*)&Bs[kk][tn0 + 4];
            unsigned long long b2[4];
            b2[0] = pk2(bb0.x, bb0.y); b2[1] = pk2(bb0.z, bb0.w);
            b2[2] = pk2(bb1.x, bb1.y); b2[3] = pk2(bb1.z, bb1.w);
#pragma unroll
            for (int i = 0; i < 8; i++) {
                unsigned long long a2 = pk2(a[i], a[i]);
#pragma unroll
                for (int j = 0; j < 4; j++) acc[i][j] = f2fma(a2, b2[j], acc[i][j]);
            }
        }
        __syncthreads();
    }

    // epilogue: unpack + vectorized store
#pragma unroll
    for (int i = 0; i < 8; i++) {
        float2 u0 = upk2(acc[i][0]), u1 = upk2(acc[i][1]);
        float2 u2 = upk2(acc[i][2]), u3 = upk2(acc[i][3]);
        float* cp = C + (long)(bm + tm0 + i) * N + bn + tn0;
        *(float4*)cp       = make_float4(u0.x, u0.y, u1.x, u1.y);
        *(float4*)(cp + 4) = make_float4(u2.x, u2.y, u3.x, u3.y);
    }
}

// ============================================================================
// Row softmax over scores, 1/sqrt(D)=1/32 scale folded in.
// One block per row (B*S rows), 256 threads, 8 elems/thread, coalesced.
// ============================================================================
__device__ __forceinline__ float warpMax(float v) {
#pragma unroll
    for (int o = 16; o; o >>= 1) v = fmaxf(v, __shfl_xor_sync(0xFFFFFFFFu, v, o));
    return v;
}
__device__ __forceinline__ float warpSum(float v) {
#pragma unroll
    for (int o = 16; o; o >>= 1) v += __shfl_xor_sync(0xFFFFFFFFu, v, o);
    return v;
}

__global__ void softmax_rows(float* __restrict__ Sc)
{
    __shared__ float red[8];
    const long row = blockIdx.x;
    float* p = Sc + row * (long)S_LEN;
    const int tid = threadIdx.x;
    const float scale = 0.03125f;  // 1/sqrt(1024)

    float v[8];
    float mx = -3.402823e38f;
#pragma unroll
    for (int i = 0; i < 8; i++) {
        v[i] = p[tid + i * 256] * scale;
        mx = fmaxf(mx, v[i]);
    }
    mx = warpMax(mx);
    if ((tid & 31) == 0) red[tid >> 5] = mx;
    __syncthreads();
    if (tid < 32) {
        float m = (tid < 8) ? red[tid] : -3.402823e38f;
        m = warpMax(m);
        if (tid == 0) red[0] = m;
    }
    __syncthreads();
    mx = red[0];
    __syncthreads();

    float s = 0.0f;
#pragma unroll
    for (int i = 0; i < 8; i++) {
        v[i] = __expf(v[i] - mx);
        s += v[i];
    }
    s = warpSum(s);
    if ((tid & 31) == 0) red[tid >> 5] = s;
    __syncthreads();
    if (tid < 32) {
        float t = (tid < 8) ? red[tid] : 0.0f;
        t = warpSum(t);
        if (tid == 0) red[0] = t;
    }
    __syncthreads();
    const float inv = 1.0f / red[0];
#pragma unroll
    for (int i = 0; i < 8; i++) p[tid + i * 256] = v[i] * inv;
}

// ============================================================================
// kernel_launch: x, Wq, Wk, Wv -> out  (all fp32)
// ============================================================================
extern "C" void kernel_launch(void* const* d_in, const int* in_sizes, int n_in,
                              void* d_out, int out_size)
{
    const float* x  = (const float*)d_in[0];
    const float* Wq = (const float*)d_in[1];
    const float* Wk = (const float*)d_in[2];
    const float* Wv = (const float*)d_in[3];
    float* out = (float*)d_out;

    float *Q, *K, *V, *Sc;
    cudaGetSymbolAddress((void**)&Q,  g_Q);
    cudaGetSymbolAddress((void**)&K,  g_K);
    cudaGetSymbolAddress((void**)&V,  g_V);
    cudaGetSymbolAddress((void**)&Sc, g_Sc);

    const int M  = BATCH * S_LEN;            // 8192
    const long SD = (long)S_LEN * D_DIM;     // 2048*1024
    const long SS = (long)S_LEN * S_LEN;     // 2048*2048

    dim3 blk(256);

    // QKV projection: [8192,1024] x [1024,1024]
    dim3 gp(D_DIM / 128, M / 128, 1);
    gemm128<false><<<gp, blk>>>(x, Wq, Q, M, D_DIM, D_DIM, 0, 0, 0);
    gemm128<false><<<gp, blk>>>(x, Wk, K, M, D_DIM, D_DIM, 0, 0, 0);
    gemm128<false><<<gp, blk>>>(x, Wv, V, M, D_DIM, D_DIM, 0, 0, 0);

    // scores = Q K^T per batch: [2048,2048] = [2048,1024] x [2048,1024]^T
    dim3 gs(S_LEN / 128, S_LEN / 128, BATCH);
    gemm128<true><<<gs, blk>>>(Q, K, Sc, S_LEN, S_LEN, D_DIM, SD, SD, SS);

    // softmax(scores / 32) row-wise
    softmax_rows<<<BATCH * S_LEN, 256>>>(Sc);

    // out = W V per batch: [2048,1024] = [2048,2048] x [2048,1024]
    dim3 ga(D_DIM / 128, S_LEN / 128, BATCH);
    gemm128<false><<<ga, blk>>>(Sc, V, out, S_LEN, D_DIM, S_LEN, SS, SD, SD);
}

// round 3
// speedup vs baseline: 1.8675x; 1.8675x over previous
#include <cuda_runtime.h>
#include <cuda_bf16.h>
#include <cstdint>

#define S_LEN 2048
#define D_DIM 1024
#define BATCH 4
#define MTOT  (BATCH * S_LEN)   // 8192

typedef __nv_bfloat16 bf16;

// ============================ device scratch ================================
__device__ bf16  g_xh [(size_t)MTOT * D_DIM];
__device__ bf16  g_xl [(size_t)MTOT * D_DIM];
__device__ bf16  g_wth[(size_t)3 * D_DIM * D_DIM];   // W^T hi (q,k,v)
__device__ bf16  g_wtl[(size_t)3 * D_DIM * D_DIM];
__device__ bf16  g_qh [(size_t)MTOT * D_DIM];
__device__ bf16  g_ql [(size_t)MTOT * D_DIM];
__device__ bf16  g_kh [(size_t)MTOT * D_DIM];
__device__ bf16  g_kl [(size_t)MTOT * D_DIM];
__device__ float g_v  [(size_t)MTOT * D_DIM];
__device__ bf16  g_vth[(size_t)BATCH * D_DIM * S_LEN];  // V^T per batch
__device__ bf16  g_vtl[(size_t)BATCH * D_DIM * S_LEN];
__device__ float g_sc [(size_t)BATCH * S_LEN * S_LEN];
__device__ bf16  g_wh [(size_t)BATCH * S_LEN * S_LEN];
__device__ bf16  g_wl [(size_t)BATCH * S_LEN * S_LEN];

// ============================ PTX helpers ===================================
__device__ __forceinline__ uint32_t smem_u32(const void* p) {
    uint32_t a;
    asm("{ .reg .u64 t; cvta.to.shared.u64 t, %1; cvt.u32.u64 %0, t; }" : "=r"(a) : "l"(p));
    return a;
}
__device__ __forceinline__ void cp16(uint32_t s, const void* g) {
    asm volatile("cp.async.cg.shared.global [%0], [%1], 16;" :: "r"(s), "l"(g) : "memory");
}
#define CP_COMMIT() asm volatile("cp.async.commit_group;" ::: "memory")
#define CP_WAIT(n)  asm volatile("cp.async.wait_group %0;" :: "n"(n) : "memory")

__device__ __forceinline__ void ldm4(uint32_t r[4], uint32_t a) {
    asm volatile("ldmatrix.sync.aligned.m8n8.x4.shared.b16 {%0,%1,%2,%3}, [%4];"
                 : "=r"(r[0]), "=r"(r[1]), "=r"(r[2]), "=r"(r[3]) : "r"(a));
}
__device__ __forceinline__ void mma16816(float c[4], const uint32_t a[4], const uint32_t b[2]) {
    asm volatile("mma.sync.aligned.m16n8k16.row.col.f32.bf16.bf16.f32 "
                 "{%0,%1,%2,%3}, {%4,%5,%6,%7}, {%8,%9}, {%0,%1,%2,%3};"
                 : "+f"(c[0]), "+f"(c[1]), "+f"(c[2]), "+f"(c[3])
                 : "r"(a[0]), "r"(a[1]), "r"(a[2]), "r"(a[3]), "r"(b[0]), "r"(b[1]));
}

// ====================== split-bf16 HMMA GEMM ================================
// C[M,N] (+z*sC) = (Ah+Al)[M,K] * (Bh+Bl)[N,K]^T   (all K-major bf16)
// EPI=0: fp32 C.  EPI=1: bf16 hi/lo split of C into Ch/Cl.
constexpr int ROW_B  = 80;            // padded smem row stride (32 bf16 + 8 pad)
constexpr int COMP_B = 128 * ROW_B;   // 10240 B per component tile
constexpr int STG_B  = 4 * COMP_B;    // 40960 B (Ah,Al,Bh,Bl)
constexpr int NSTG   = 3;
constexpr int SMEM_SZ = NSTG * STG_B; // 122880 B

__device__ __forceinline__ void load_stage(uint32_t base,
    const bf16* __restrict__ ah, const bf16* __restrict__ al,
    const bf16* __restrict__ bh, const bf16* __restrict__ bl,
    int bm, int bn, int kt, int K, int tid)
{
    const int r  = tid >> 2;               // 0..63
    const int c  = tid & 3;                // 16B chunk in row
    const int kc = kt * 32 + c * 8;
    const uint32_t so = (uint32_t)r * ROW_B + c * 16;
    const long ga0 = (long)(bm + r) * K + kc;
    const long ga1 = (long)(bm + r + 64) * K + kc;
    const long gb0 = (long)(bn + r) * K + kc;
    const long gb1 = (long)(bn + r + 64) * K + kc;
    cp16(base + so,                        ah + ga0);
    cp16(base + so + 64 * ROW_B,           ah + ga1);
    cp16(base + COMP_B + so,               al + ga0);
    cp16(base + COMP_B + so + 64 * ROW_B,  al + ga1);
    cp16(base + 2*COMP_B + so,             bh + gb0);
    cp16(base + 2*COMP_B + so + 64*ROW_B,  bh + gb1);
    cp16(base + 3*COMP_B + so,             bl + gb0);
    cp16(base + 3*COMP_B + so + 64*ROW_B,  bl + gb1);
}

template <int EPI>
__global__ void __launch_bounds__(256, 1)
gemm_mma(const bf16* __restrict__ Agh, const bf16* __restrict__ Agl,
         const bf16* __restrict__ Bgh, const bf16* __restrict__ Bgl,
         float* __restrict__ C, bf16* __restrict__ Ch, bf16* __restrict__ Cl,
         int N, int K, long sA, long sB, long sC)
{
    extern __shared__ __align__(128) char smem[];
    const uint32_t sb = smem_u32(smem);
    const int tid = threadIdx.x, lane = tid & 31, warp = tid >> 5;
    const int wm = warp >> 2, wn = warp & 3;          // 2 x 4 warp grid
    const int bm = blockIdx.y * 128, bn = blockIdx.x * 128, z = blockIdx.z;

    const bf16* Ah = Agh + (long)z * sA;
    const bf16* Al = Agl + (long)z * sA;
    const bf16* Bh = Bgh + (long)z * sB;
    const bf16* Bl = Bgl + (long)z * sB;

    const int nk = K >> 5;

    // ldmatrix per-thread address components (16B aligned; stride-80 rows are
    // bank-conflict-free: 8 consecutive rows hit bank sets 0,20,8,28,16,4,24,12)
    const uint32_t aOff = (uint32_t)(wm * 64 + (lane & 15)) * ROW_B + ((lane >> 4) & 1) * 16;
    const uint32_t bRow = (uint32_t)((lane & 7) | (((lane >> 4) & 1) << 3));
    const uint32_t bOff = (uint32_t)(wn * 32 + bRow) * ROW_B + ((lane >> 3) & 1) * 16;

    float acc[4][4][4];
#pragma unroll
    for (int i = 0; i < 4; i++)
#pragma unroll
        for (int j = 0; j < 4; j++)
#pragma unroll
            for (int q = 0; q < 4; q++) acc[i][j][q] = 0.0f;

    // prologue: fill NSTG stages (nk >= 32 always)
#pragma unroll
    for (int s = 0; s < NSTG; s++) {
        load_stage(sb + s * STG_B, Ah, Al, Bh, Bl, bm, bn, s, K, tid);
        CP_COMMIT();
    }

    for (int kt = 0; kt < nk; kt++) {
        CP_WAIT(NSTG - 1);
        __syncthreads();

        const uint32_t st = sb + (kt % NSTG) * STG_B;
#pragma unroll
        for (int k16 = 0; k16 < 2; k16++) {
            const uint32_t ka = k16 * 32;   // 16 bf16 = 32 B
            uint32_t ah[4][4], al[4][4], bh[2][4], bl[2][4];
#pragma unroll
            for (int mi = 0; mi < 4; mi++) {
                ldm4(ah[mi], st + aOff + mi * 16 * ROW_B + ka);
                ldm4(al[mi], st + COMP_B + aOff + mi * 16 * ROW_B + ka);
            }
#pragma unroll
            for (int nb = 0; nb < 2; nb++) {
                ldm4(bh[nb], st + 2 * COMP_B + bOff + nb * 16 * ROW_B + ka);
                ldm4(bl[nb], st + 3 * COMP_B + bOff + nb * 16 * ROW_B + ka);
            }
#pragma unroll
            for (int mi = 0; mi < 4; mi++)
#pragma unroll
                for (int ni = 0; ni < 4; ni++) {
                    const uint32_t* bhp = &bh[ni >> 1][(ni & 1) * 2];
                    const uint32_t* blp = &bl[ni >> 1][(ni & 1) * 2];
                    mma16816(acc[mi][ni], ah[mi], bhp);  // hi*hi
                    mma16816(acc[mi][ni], ah[mi], blp);  // hi*lo
                    mma16816(acc[mi][ni], al[mi], bhp);  // lo*hi
                }
        }
        __syncthreads();

        const int nx = kt + NSTG;
        if (nx < nk)
            load_stage(sb + (kt % NSTG) * STG_B, Ah, Al, Bh, Bl, bm, bn, nx, K, tid);
        CP_COMMIT();   // unconditional: keeps wait_group accounting exact
    }

    // ---- epilogue ----
    const int qr = lane >> 2, qc = (lane & 3) * 2;
#pragma unroll
    for (int mi = 0; mi < 4; mi++)
#pragma unroll
        for (int ni = 0; ni < 4; ni++) {
            const int m = bm + wm * 64 + mi * 16 + qr;
            const int n = bn + wn * 32 + ni * 8 + qc;
            const long o0 = (long)z * sC + (long)m * N + n;
            const long o1 = o0 + 8L * N;
            if (EPI == 0) {
                *(float2*)(C + o0) = make_float2(acc[mi][ni][0], acc[mi][ni][1]);
                *(float2*)(C + o1) = make_float2(acc[mi][ni][2], acc[mi][ni][3]);
            } else {
                float x0 = acc[mi][ni][0], y0 = acc[mi][ni][1];
                float x1 = acc[mi][ni][2], y1 = acc[mi][ni][3];
                bf16 hx0 = __float2bfloat16(x0), hy0 = __float2bfloat16(y0);
                bf16 hx1 = __float2bfloat16(x1), hy1 = __float2bfloat16(y1);
                *(__nv_bfloat162*)(Ch + o0) = __nv_bfloat162(hx0, hy0);
                *(__nv_bfloat162*)(Ch + o1) = __nv_bfloat162(hx1, hy1);
                *(__nv_bfloat162*)(Cl + o0) = __nv_bfloat162(
                    __float2bfloat16(x0 - __bfloat162float(hx0)),
                    __float2bfloat16(y0 - __bfloat162float(hy0)));
                *(__nv_bfloat162*)(Cl + o1) = __nv_bfloat162(
                    __float2bfloat16(x1 - __bfloat162float(hx1)),
                    __float2bfloat16(y1 - __bfloat162float(hy1)));
            }
        }
}

// =========================== prep kernels ===================================
__global__ void split_f32(const float* __restrict__ in, bf16* __restrict__ oh,
                          bf16* __restrict__ ol)
{
    long i = ((long)blockIdx.x * 256 + threadIdx.x) * 4;
    float4 f = *(const float4*)(in + i);
    bf16 h0 = __float2bfloat16(f.x), h1 = __float2bfloat16(f.y);
    bf16 h2 = __float2bfloat16(f.z), h3 = __float2bfloat16(f.w);
    __nv_bfloat162* hp = (__nv_bfloat162*)(oh + i);
    __nv_bfloat162* lp = (__nv_bfloat162*)(ol + i);
    hp[0] = __nv_bfloat162(h0, h1);
    hp[1] = __nv_bfloat162(h2, h3);
    lp[0] = __nv_bfloat162(__float2bfloat16(f.x - __bfloat162float(h0)),
                           __float2bfloat16(f.y - __bfloat162float(h1)));
    lp[1] = __nv_bfloat162(__float2bfloat16(f.z - __bfloat162float(h2)),
                           __float2bfloat16(f.w - __bfloat162float(h3)));
}

// transpose [R,C] -> [C,R] with hi/lo bf16 split; z batches via strides
__global__ void tsplit(const float* __restrict__ in, bf16* __restrict__ oh,
                       bf16* __restrict__ ol, int R, int C, long sIn, long sOut)
{
    __shared__ float t[32][33];
    const int bx = blockIdx.x * 32, by = blockIdx.y * 32;
    const float* ip = in + (long)blockIdx.z * sIn;
    bf16* ohp = oh + (long)blockIdx.z * sOut;
    bf16* olp = ol + (long)blockIdx.z * sOut;
    const int tx = threadIdx.x;
#pragma unroll
    for (int i = threadIdx.y; i < 32; i += 8)
        t[i][tx] = ip[(long)(by + i) * C + bx + tx];
    __syncthreads();
#pragma unroll
    for (int i = threadIdx.y; i < 32; i += 8) {
        float f = t[tx][i];
        bf16 h = __float2bfloat16(f);
        long o = (long)(bx + i) * R + by + tx;
        ohp[o] = h;
        olp[o] = __float2bfloat16(f - __bfloat162float(h));
    }
}

// ============================ softmax =======================================
__device__ __forceinline__ float warpMax(float v) {
#pragma unroll
    for (int o = 16; o; o >>= 1) v = fmaxf(v, __shfl_xor_sync(0xFFFFFFFFu, v, o));
    return v;
}
__device__ __forceinline__ float warpSum(float v) {
#pragma unroll
    for (int o = 16; o; o >>= 1) v += __shfl_xor_sync(0xFFFFFFFFu, v, o);
    return v;
}

__global__ void softmax_rows(const float* __restrict__ Sc,
                             bf16* __restrict__ Wh, bf16* __restrict__ Wl)
{
    __shared__ float red[8];
    const long row = blockIdx.x;
    const float* p = Sc + row * (long)S_LEN;
    const int tid = threadIdx.x;
    const float scale = 0.03125f;  // 1/sqrt(1024)

    float v[8];
    float mx = -3.402823e38f;
#pragma unroll
    for (int i = 0; i < 8; i++) {
        v[i] = p[tid + i * 256] * scale;
        mx = fmaxf(mx, v[i]);
    }
    mx = warpMax(mx);
    if ((tid & 31) == 0) red[tid >> 5] = mx;
    __syncthreads();
    if (tid < 32) {
        float m = (tid < 8) ? red[tid] : -3.402823e38f;
        m = warpMax(m);
        if (tid == 0) red[0] = m;
    }
    __syncthreads();
    mx = red[0];
    __syncthreads();

    float s = 0.0f;
#pragma unroll
    for (int i = 0; i < 8; i++) { v[i] = __expf(v[i] - mx); s += v[i]; }
    s = warpSum(s);
    if ((tid & 31) == 0) red[tid >> 5] = s;
    __syncthreads();
    if (tid < 32) {
        float t = (tid < 8) ? red[tid] : 0.0f;
        t = warpSum(t);
        if (tid == 0) red[0] = t;
    }
    __syncthreads();
    const float inv = 1.0f / red[0];
#pragma unroll
    for (int i = 0; i < 8; i++) {
        float w = v[i] * inv;
        bf16 h = __float2bfloat16(w);
        Wh[row * (long)S_LEN + tid + i * 256] = h;
        Wl[row * (long)S_LEN + tid + i * 256] =
            __float2bfloat16(w - __bfloat162float(h));
    }
}

// ============================ host side =====================================
extern "C" void kernel_launch(void* const* d_in, const int* in_sizes, int n_in,
                              void* d_out, int out_size)
{
    const float* x  = (const float*)d_in[0];
    const float* Wq = (const float*)d_in[1];
    const float* Wk = (const float*)d_in[2];
    const float* Wv = (const float*)d_in[3];
    float* out = (float*)d_out;

    void *xh, *xl, *wth, *wtl, *qh, *ql, *kh, *kl, *v, *vth, *vtl, *sc, *wh, *wl;
    cudaGetSymbolAddress(&xh, g_xh);   cudaGetSymbolAddress(&xl, g_xl);
    cudaGetSymbolAddress(&wth, g_wth); cudaGetSymbolAddress(&wtl, g_wtl);
    cudaGetSymbolAddress(&qh, g_qh);   cudaGetSymbolAddress(&ql, g_ql);
    cudaGetSymbolAddress(&kh, g_kh);   cudaGetSymbolAddress(&kl, g_kl);
    cudaGetSymbolAddress(&v, g_v);
    cudaGetSymbolAddress(&vth, g_vth); cudaGetSymbolAddress(&vtl, g_vtl);
    cudaGetSymbolAddress(&sc, g_sc);
    cudaGetSymbolAddress(&wh, g_wh);   cudaGetSymbolAddress(&wl, g_wl);

    cudaFuncSetAttribute(gemm_mma<0>, cudaFuncAttributeMaxDynamicSharedMemorySize, SMEM_SZ);
    cudaFuncSetAttribute(gemm_mma<1>, cudaFuncAttributeMaxDynamicSharedMemorySize, SMEM_SZ);

    const long SD = (long)S_LEN * D_DIM, SS = (long)S_LEN * S_LEN;
    const long W1 = (long)D_DIM * D_DIM;

    // ---- data prep ----
    split_f32<<<(int)((long)MTOT * D_DIM / 1024), 256>>>(x, (bf16*)xh, (bf16*)xl);
    dim3 tb(32, 8);
    tsplit<<<dim3(32, 32, 1), tb>>>(Wq, (bf16*)wth,          (bf16*)wtl,          D_DIM, D_DIM, 0, 0);
    tsplit<<<dim3(32, 32, 1), tb>>>(Wk, (bf16*)wth + W1,     (bf16*)wtl + W1,     D_DIM, D_DIM, 0, 0);
    tsplit<<<dim3(32, 32, 1), tb>>>(Wv, (bf16*)wth + 2 * W1, (bf16*)wtl + 2 * W1, D_DIM, D_DIM, 0, 0);

    // ---- QKV projections: [8192,1024] = x * W^T ----
    dim3 gp(D_DIM / 128, MTOT / 128, 1);
    gemm_mma<1><<<gp, 256, SMEM_SZ>>>((bf16*)xh, (bf16*)xl, (bf16*)wth, (bf16*)wtl,
        nullptr, (bf16*)qh, (bf16*)ql, D_DIM, D_DIM, 0, 0, 0);
    gemm_mma<1><<<gp, 256, SMEM_SZ>>>((bf16*)xh, (bf16*)xl, (bf16*)wth + W1, (bf16*)wtl + W1,
        nullptr, (bf16*)kh, (bf16*)kl, D_DIM, D_DIM, 0, 0, 0);
    gemm_mma<0><<<gp, 256, SMEM_SZ>>>((bf16*)xh, (bf16*)xl, (bf16*)wth + 2 * W1, (bf16*)wtl + 2 * W1,
        (float*)v, nullptr, nullptr, D_DIM, D_DIM, 0, 0, 0);

    // V -> V^T hi/lo per batch
    tsplit<<<dim3(D_DIM / 32, S_LEN / 32, BATCH), tb>>>(
        (const float*)v, (bf16*)vth, (bf16*)vtl, S_LEN, D_DIM, SD, SD);

    // scores = Q K^T per batch
    dim3 gs(S_LEN / 128, S_LEN / 128, BATCH);
    gemm_mma<0><<<gs, 256, SMEM_SZ>>>((bf16*)qh, (bf16*)ql, (bf16*)kh, (bf16*)kl,
        (float*)sc, nullptr, nullptr, S_LEN, D_DIM, SD, SD, SS);

    softmax_rows<<<BATCH * S_LEN, 256>>>((const float*)sc, (bf16*)wh, (bf16*)wl);

    // out = softmaxW * V  (B = V^T, K-major)
    dim3 ga(D_DIM / 128, S_LEN / 128, BATCH);
    gemm_mma<0><<<ga, 256, SMEM_SZ>>>((bf16*)wh, (bf16*)wl, (bf16*)vth, (bf16*)vtl,
        out, nullptr, nullptr, D_DIM, S_LEN, SS, SD, SD);
}

// round 5
// speedup vs baseline: 2.5940x; 1.3890x over previous
#include <cuda_runtime.h>
#include <cuda_bf16.h>
#include <cstdint>

#define S_LEN 2048
#define D_DIM 1024
#define BATCH 4
#define MTOT  (BATCH * S_LEN)   // 8192

typedef __nv_bfloat16 bf16;

// ============================ device scratch ================================
__device__ bf16  g_xh [(size_t)MTOT * D_DIM];
__device__ bf16  g_xl [(size_t)MTOT * D_DIM];
__device__ bf16  g_wth[(size_t)3 * D_DIM * D_DIM];   // W^T hi (q,k,v)
__device__ bf16  g_wtl[(size_t)3 * D_DIM * D_DIM];
__device__ bf16  g_qh [(size_t)MTOT * D_DIM];
__device__ bf16  g_ql [(size_t)MTOT * D_DIM];
__device__ bf16  g_kh [(size_t)MTOT * D_DIM];
__device__ bf16  g_kl [(size_t)MTOT * D_DIM];
__device__ float g_v  [(size_t)MTOT * D_DIM];
__device__ bf16  g_vth[(size_t)BATCH * D_DIM * S_LEN];  // V^T per batch
__device__ bf16  g_vtl[(size_t)BATCH * D_DIM * S_LEN];
__device__ float g_sc [(size_t)BATCH * S_LEN * S_LEN];
__device__ bf16  g_wh [(size_t)BATCH * S_LEN * S_LEN];
__device__ bf16  g_wl [(size_t)BATCH * S_LEN * S_LEN];

// ============================ PTX helpers ===================================
__device__ __forceinline__ uint32_t smem_u32(const void* p) {
    uint32_t a;
    asm("{ .reg .u64 t; cvta.to.shared.u64 t, %1; cvt.u32.u64 %0, t; }" : "=r"(a) : "l"(p));
    return a;
}
__device__ __forceinline__ void cp16(uint32_t s, const void* g) {
    asm volatile("cp.async.cg.shared.global [%0], [%1], 16;" :: "r"(s), "l"(g) : "memory");
}
#define CP_COMMIT() asm volatile("cp.async.commit_group;" ::: "memory")
#define CP_WAIT(n)  asm volatile("cp.async.wait_group %0;" :: "n"(n) : "memory")

__device__ __forceinline__ void ldm4(uint32_t r[4], uint32_t a) {
    asm volatile("ldmatrix.sync.aligned.m8n8.x4.shared.b16 {%0,%1,%2,%3}, [%4];"
                 : "=r"(r[0]), "=r"(r[1]), "=r"(r[2]), "=r"(r[3]) : "r"(a));
}
__device__ __forceinline__ void mma16816(float c[4], const uint32_t a[4], const uint32_t b[2]) {
    asm volatile("mma.sync.aligned.m16n8k16.row.col.f32.bf16.bf16.f32 "
                 "{%0,%1,%2,%3}, {%4,%5,%6,%7}, {%8,%9}, {%0,%1,%2,%3};"
                 : "+f"(c[0]), "+f"(c[1]), "+f"(c[2]), "+f"(c[3])
                 : "r"(a[0]), "r"(a[1]), "r"(a[2]), "r"(a[3]), "r"(b[0]), "r"(b[1]));
}

// ====================== split-bf16 HMMA GEMM ================================
// C[M,N] (+z*sC) = (Ah+Al)[M,K] * (Bh+Bl)[N,K]^T   (all K-major bf16)
// CTA 128x128x32, 128 threads, 4 warps of 64x64. 2 CTAs/SM (192KB smem total).
// Smem: unpadded 64B rows with XOR chunk swizzle: phys_chunk = c ^ ((row>>1)&3).
//  - cp.async dst stays 16B aligned (64B rows, 16B chunks)
//  - ldmatrix phase (8 consecutive rows, same logical chunk) tiles all 32 banks
// EPI=0: fp32 C.  EPI=1: bf16 hi/lo split of C into Ch/Cl.
constexpr int ROW_B  = 64;            // 32 bf16, no pad (swizzled)
constexpr int COMP_B = 128 * ROW_B;   // 8192 B per component tile
constexpr int STG_B  = 4 * COMP_B;    // 32768 B (Ah,Al,Bh,Bl)
constexpr int NSTG   = 3;
constexpr int SMEM_SZ = NSTG * STG_B; // 98304 B -> 2 CTAs/SM

__device__ __forceinline__ void load_stage(uint32_t base,
    const bf16* __restrict__ ah, const bf16* __restrict__ al,
    const bf16* __restrict__ bh, const bf16* __restrict__ bl,
    int bm, int bn, int kt, int K, int tid)
{
    const int r  = tid >> 2;               // 0..31
    const int c  = tid & 3;                // logical 16B chunk in row
    const int kc = kt * 32 + c * 8;
    const int cp = c ^ ((r >> 1) & 3);     // swizzled chunk (row>>1)&3 invariant to +32 rows
#pragma unroll
    for (int g = 0; g < 4; g++) {          // row groups r, r+32, r+64, r+96
        const int row = r + g * 32;
        const uint32_t so = (uint32_t)row * ROW_B + cp * 16;
        const long ga = (long)(bm + row) * K + kc;
        const long gb = (long)(bn + row) * K + kc;
        cp16(base + so,              ah + ga);
        cp16(base + COMP_B + so,     al + ga);
        cp16(base + 2 * COMP_B + so, bh + gb);
        cp16(base + 3 * COMP_B + so, bl + gb);
    }
}

template <int EPI>
__global__ void __launch_bounds__(128, 2)
gemm_mma(const bf16* __restrict__ Agh, const bf16* __restrict__ Agl,
         const bf16* __restrict__ Bgh, const bf16* __restrict__ Bgl,
         float* __restrict__ C, bf16* __restrict__ Ch, bf16* __restrict__ Cl,
         int N, int K, long sA, long sB, long sC)
{
    extern __shared__ __align__(128) char smem[];
    const uint32_t sb = smem_u32(smem);
    const int tid = threadIdx.x, lane = tid & 31, warp = tid >> 5;
    const int wm = warp >> 1, wn = warp & 1;          // 2 x 2 warp grid, 64x64 tiles
    const int bm = blockIdx.y * 128, bn = blockIdx.x * 128, z = blockIdx.z;

    const bf16* Ah = Agh + (long)z * sA;
    const bf16* Al = Agl + (long)z * sA;
    const bf16* Bh = Bgh + (long)z * sB;
    const bf16* Bl = Bgl + (long)z * sB;

    const int nk = K >> 5;

    // ldmatrix per-thread address components.
    // A: row = wm*64 + (lane&15) (+16*mi), logical chunk = k16*2 + bit4(lane)
    // B: row = wn*64 + bRow (+16*nb),      logical chunk = k16*2 + bit3(lane)
    // swizzle term (row>>1)&3 is invariant under +16-row steps.
    const uint32_t aRow = (uint32_t)(wm * 64 + (lane & 15));
    const uint32_t aSw  = (aRow >> 1) & 3;
    const uint32_t aC0  = (uint32_t)((lane >> 4) & 1);
    const uint32_t bRow0 = (uint32_t)((lane & 7) | (((lane >> 4) & 1) << 3));
    const uint32_t bRow = (uint32_t)(wn * 64) + bRow0;
    const uint32_t bSw  = (bRow0 >> 1) & 3;
    const uint32_t bC0  = (uint32_t)((lane >> 3) & 1);

    float acc[4][8][4];
#pragma unroll
    for (int i = 0; i < 4; i++)
#pragma unroll
        for (int j = 0; j < 8; j++)
#pragma unroll
            for (int q = 0; q < 4; q++) acc[i][j][q] = 0.0f;

    // prologue: fill NSTG stages (nk >= 32 always)
#pragma unroll
    for (int s = 0; s < NSTG; s++) {
        load_stage(sb + s * STG_B, Ah, Al, Bh, Bl, bm, bn, s, K, tid);
        CP_COMMIT();
    }

    for (int kt = 0; kt < nk; kt++) {
        CP_WAIT(NSTG - 1);
        __syncthreads();

        const uint32_t st = sb + (kt % NSTG) * STG_B;
#pragma unroll
        for (int k16 = 0; k16 < 2; k16++) {
            const uint32_t aCk = ((uint32_t)(k16 * 2) + aC0) ^ aSw;   // phys chunk
            const uint32_t bCk = ((uint32_t)(k16 * 2) + bC0) ^ bSw;
            const uint32_t aAddr = st + aRow * ROW_B + aCk * 16;
            const uint32_t bAddr = st + 2 * COMP_B + bRow * ROW_B + bCk * 16;
            uint32_t ah[4][4], al[4][4], bh[4][4], bl[4][4];
#pragma unroll
            for (int mi = 0; mi < 4; mi++) {
                ldm4(ah[mi], aAddr + mi * 16 * ROW_B);
                ldm4(al[mi], aAddr + COMP_B + mi * 16 * ROW_B);
            }
#pragma unroll
            for (int nb = 0; nb < 4; nb++) {
                ldm4(bh[nb], bAddr + nb * 16 * ROW_B);
                ldm4(bl[nb], bAddr + COMP_B + nb * 16 * ROW_B);
            }
#pragma unroll
            for (int mi = 0; mi < 4; mi++)
#pragma unroll
                for (int ni = 0; ni < 8; ni++) {
                    const uint32_t* bhp = &bh[ni >> 1][(ni & 1) * 2];
                    const uint32_t* blp = &bl[ni >> 1][(ni & 1) * 2];
                    mma16816(acc[mi][ni], ah[mi], bhp);  // hi*hi
                    mma16816(acc[mi][ni], ah[mi], blp);  // hi*lo
                    mma16816(acc[mi][ni], al[mi], bhp);  // lo*hi
                }
        }
        __syncthreads();

        const int nx = kt + NSTG;
        if (nx < nk)
            load_stage(sb + (kt % NSTG) * STG_B, Ah, Al, Bh, Bl, bm, bn, nx, K, tid);
        CP_COMMIT();   // unconditional: keeps wait_group accounting exact
    }

    // ---- epilogue ----
    const int qr = lane >> 2, qc = (lane & 3) * 2;
#pragma unroll
    for (int mi = 0; mi < 4; mi++)
#pragma unroll
        for (int ni = 0; ni < 8; ni++) {
            const int m = bm + wm * 64 + mi * 16 + qr;
            const int n = bn + wn * 64 + ni * 8 + qc;
            const long o0 = (long)z * sC + (long)m * N + n;
            const long o1 = o0 + 8L * N;
            if (EPI == 0) {
                *(float2*)(C + o0) = make_float2(acc[mi][ni][0], acc[mi][ni][1]);
                *(float2*)(C + o1) = make_float2(acc[mi][ni][2], acc[mi][ni][3]);
            } else {
                float x0 = acc[mi][ni][0], y0 = acc[mi][ni][1];
                float x1 = acc[mi][ni][2], y1 = acc[mi][ni][3];
                bf16 hx0 = __float2bfloat16(x0), hy0 = __float2bfloat16(y0);
                bf16 hx1 = __float2bfloat16(x1), hy1 = __float2bfloat16(y1);
                *(__nv_bfloat162*)(Ch + o0) = __nv_bfloat162(hx0, hy0);
                *(__nv_bfloat162*)(Ch + o1) = __nv_bfloat162(hx1, hy1);
                *(__nv_bfloat162*)(Cl + o0) = __nv_bfloat162(
                    __float2bfloat16(x0 - __bfloat162float(hx0)),
                    __float2bfloat16(y0 - __bfloat162float(hy0)));
                *(__nv_bfloat162*)(Cl + o1) = __nv_bfloat162(
                    __float2bfloat16(x1 - __bfloat162float(hx1)),
                    __float2bfloat16(y1 - __bfloat162float(hy1)));
            }
        }
}

// =========================== prep kernels ===================================
__global__ void split_f32(const float* __restrict__ in, bf16* __restrict__ oh,
                          bf16* __restrict__ ol)
{
    long i = ((long)blockIdx.x * 256 + threadIdx.x) * 4;
    float4 f = *(const float4*)(in + i);
    bf16 h0 = __float2bfloat16(f.x), h1 = __float2bfloat16(f.y);
    bf16 h2 = __float2bfloat16(f.z), h3 = __float2bfloat16(f.w);
    __nv_bfloat162* hp = (__nv_bfloat162*)(oh + i);
    __nv_bfloat162* lp = (__nv_bfloat162*)(ol + i);
    hp[0] = __nv_bfloat162(h0, h1);
    hp[1] = __nv_bfloat162(h2, h3);
    lp[0] = __nv_bfloat162(__float2bfloat16(f.x - __bfloat162float(h0)),
                           __float2bfloat16(f.y - __bfloat162float(h1)));
    lp[1] = __nv_bfloat162(__float2bfloat16(f.z - __bfloat162float(h2)),
                           __float2bfloat16(f.w - __bfloat162float(h3)));
}

// transpose [R,C] -> [C,R] with hi/lo bf16 split; z batches via strides
__global__ void tsplit(const float* __restrict__ in, bf16* __restrict__ oh,
                       bf16* __restrict__ ol, int R, int C, long sIn, long sOut)
{
    __shared__ float t[32][33];
    const int bx = blockIdx.x * 32, by = blockIdx.y * 32;
    const float* ip = in + (long)blockIdx.z * sIn;
    bf16* ohp = oh + (long)blockIdx.z * sOut;
    bf16* olp = ol + (long)blockIdx.z * sOut;
    const int tx = threadIdx.x;
#pragma unroll
    for (int i = threadIdx.y; i < 32; i += 8)
        t[i][tx] = ip[(long)(by + i) * C + bx + tx];
    __syncthreads();
#pragma unroll
    for (int i = threadIdx.y; i < 32; i += 8) {
        float f = t[tx][i];
        bf16 h = __float2bfloat16(f);
        long o = (long)(bx + i) * R + by + tx;
        ohp[o] = h;
        olp[o] = __float2bfloat16(f - __bfloat162float(h));
    }
}

// ============================ softmax =======================================
__device__ __forceinline__ float warpMax(float v) {
#pragma unroll
    for (int o = 16; o; o >>= 1) v = fmaxf(v, __shfl_xor_sync(0xFFFFFFFFu, v, o));
    return v;
}
__device__ __forceinline__ float warpSum(float v) {
#pragma unroll
    for (int o = 16; o; o >>= 1) v += __shfl_xor_sync(0xFFFFFFFFu, v, o);
    return v;
}

__global__ void softmax_rows(const float* __restrict__ Sc,
                             bf16* __restrict__ Wh, bf16* __restrict__ Wl)
{
    __shared__ float red[8];
    const long row = blockIdx.x;
    const float* p = Sc + row * (long)S_LEN;
    const int tid = threadIdx.x;
    const float scale = 0.03125f;  // 1/sqrt(1024)

    float v[8];
    float mx = -3.402823e38f;
#pragma unroll
    for (int i = 0; i < 8; i++) {
        v[i] = p[tid + i * 256] * scale;
        mx = fmaxf(mx, v[i]);
    }
    mx = warpMax(mx);
    if ((tid & 31) == 0) red[tid >> 5] = mx;
    __syncthreads();
    if (tid < 32) {
        float m = (tid < 8) ? red[tid] : -3.402823e38f;
        m = warpMax(m);
        if (tid == 0) red[0] = m;
    }
    __syncthreads();
    mx = red[0];
    __syncthreads();

    float s = 0.0f;
#pragma unroll
    for (int i = 0; i < 8; i++) { v[i] = __expf(v[i] - mx); s += v[i]; }
    s = warpSum(s);
    if ((tid & 31) == 0) red[tid >> 5] = s;
    __syncthreads();
    if (tid < 32) {
        float t = (tid < 8) ? red[tid] : 0.0f;
        t = warpSum(t);
        if (tid == 0) red[0] = t;
    }
    __syncthreads();
    const float inv = 1.0f / red[0];
#pragma unroll
    for (int i = 0; i < 8; i++) {
        float w = v[i] * inv;
        bf16 h = __float2bfloat16(w);
        Wh[row * (long)S_LEN + tid + i * 256] = h;
        Wl[row * (long)S_LEN + tid + i * 256] =
            __float2bfloat16(w - __bfloat162float(h));
    }
}

// ============================ host side =====================================
extern "C" void kernel_launch(void* const* d_in, const int* in_sizes, int n_in,
                              void* d_out, int out_size)
{
    const float* x  = (const float*)d_in[0];
    const float* Wq = (const float*)d_in[1];
    const float* Wk = (const float*)d_in[2];
    const float* Wv = (const float*)d_in[3];
    float* out = (float*)d_out;

    void *xh, *xl, *wth, *wtl, *qh, *ql, *kh, *kl, *v, *vth, *vtl, *sc, *wh, *wl;
    cudaGetSymbolAddress(&xh, g_xh);   cudaGetSymbolAddress(&xl, g_xl);
    cudaGetSymbolAddress(&wth, g_wth); cudaGetSymbolAddress(&wtl, g_wtl);
    cudaGetSymbolAddress(&qh, g_qh);   cudaGetSymbolAddress(&ql, g_ql);
    cudaGetSymbolAddress(&kh, g_kh);   cudaGetSymbolAddress(&kl, g_kl);
    cudaGetSymbolAddress(&v, g_v);
    cudaGetSymbolAddress(&vth, g_vth); cudaGetSymbolAddress(&vtl, g_vtl);
    cudaGetSymbolAddress(&sc, g_sc);
    cudaGetSymbolAddress(&wh, g_wh);   cudaGetSymbolAddress(&wl, g_wl);

    cudaFuncSetAttribute(gemm_mma<0>, cudaFuncAttributeMaxDynamicSharedMemorySize, SMEM_SZ);
    cudaFuncSetAttribute(gemm_mma<1>, cudaFuncAttributeMaxDynamicSharedMemorySize, SMEM_SZ);

    const long SD = (long)S_LEN * D_DIM, SS = (long)S_LEN * S_LEN;
    const long W1 = (long)D_DIM * D_DIM;

    // ---- data prep ----
    split_f32<<<(int)((long)MTOT * D_DIM / 1024), 256>>>(x, (bf16*)xh, (bf16*)xl);
    dim3 tb(32, 8);
    tsplit<<<dim3(32, 32, 1), tb>>>(Wq, (bf16*)wth,          (bf16*)wtl,          D_DIM, D_DIM, 0, 0);
    tsplit<<<dim3(32, 32, 1), tb>>>(Wk, (bf16*)wth + W1,     (bf16*)wtl + W1,     D_DIM, D_DIM, 0, 0);
    tsplit<<<dim3(32, 32, 1), tb>>>(Wv, (bf16*)wth + 2 * W1, (bf16*)wtl + 2 * W1, D_DIM, D_DIM, 0, 0);

    // ---- QKV projections: [8192,1024] = x * W^T ----
    dim3 gp(D_DIM / 128, MTOT / 128, 1);
    gemm_mma<1><<<gp, 128, SMEM_SZ>>>((bf16*)xh, (bf16*)xl, (bf16*)wth, (bf16*)wtl,
        nullptr, (bf16*)qh, (bf16*)ql, D_DIM, D_DIM, 0, 0, 0);
    gemm_mma<1><<<gp, 128, SMEM_SZ>>>((bf16*)xh, (bf16*)xl, (bf16*)wth + W1, (bf16*)wtl + W1,
        nullptr, (bf16*)kh, (bf16*)kl, D_DIM, D_DIM, 0, 0, 0);
    gemm_mma<0><<<gp, 128, SMEM_SZ>>>((bf16*)xh, (bf16*)xl, (bf16*)wth + 2 * W1, (bf16*)wtl + 2 * W1,
        (float*)v, nullptr, nullptr, D_DIM, D_DIM, 0, 0, 0);

    // V -> V^T hi/lo per batch
    tsplit<<<dim3(D_DIM / 32, S_LEN / 32, BATCH), tb>>>(
        (const float*)v, (bf16*)vth, (bf16*)vtl, S_LEN, D_DIM, SD, SD);

    // scores = Q K^T per batch
    dim3 gs(S_LEN / 128, S_LEN / 128, BATCH);
    gemm_mma<0><<<gs, 128, SMEM_SZ>>>((bf16*)qh, (bf16*)ql, (bf16*)kh, (bf16*)kl,
        (float*)sc, nullptr, nullptr, S_LEN, D_DIM, SD, SD, SS);

    softmax_rows<<<BATCH * S_LEN, 256>>>((const float*)sc, (bf16*)wh, (bf16*)wl);

    // out = softmaxW * V  (B = V^T, K-major)
    dim3 ga(D_DIM / 128, S_LEN / 128, BATCH);
    gemm_mma<0><<<ga, 128, SMEM_SZ>>>((bf16*)wh, (bf16*)wl, (bf16*)vth, (bf16*)vtl,
        out, nullptr, nullptr, D_DIM, S_LEN, SS, SD, SD);
}

// round 6
// speedup vs baseline: 2.7520x; 1.0609x over previous
#include <cuda_runtime.h>
#include <cuda_bf16.h>
#include <cstdint>

#define S_LEN 2048
#define D_DIM 1024
#define BATCH 4
#define MTOT  (BATCH * S_LEN)   // 8192

typedef __nv_bfloat16 bf16;

// ============================ device scratch ================================
__device__ bf16  g_xh [(size_t)MTOT * D_DIM];
__device__ bf16  g_xl [(size_t)MTOT * D_DIM];
__device__ bf16  g_wth[(size_t)3 * D_DIM * D_DIM];   // W^T hi (q,k,v) contiguous
__device__ bf16  g_wtl[(size_t)3 * D_DIM * D_DIM];
__device__ bf16  g_qh [(size_t)MTOT * D_DIM];
__device__ bf16  g_ql [(size_t)MTOT * D_DIM];
__device__ bf16  g_kh [(size_t)MTOT * D_DIM];
__device__ bf16  g_kl [(size_t)MTOT * D_DIM];
__device__ float g_v  [(size_t)MTOT * D_DIM];
__device__ bf16  g_vth[(size_t)BATCH * D_DIM * S_LEN];  // V^T per batch
__device__ bf16  g_vtl[(size_t)BATCH * D_DIM * S_LEN];
__device__ float g_sc [(size_t)BATCH * S_LEN * S_LEN];
__device__ bf16  g_wh [(size_t)BATCH * S_LEN * S_LEN];
__device__ bf16  g_wl [(size_t)BATCH * S_LEN * S_LEN];

// ============================ PTX helpers ===================================
__device__ __forceinline__ uint32_t smem_u32(const void* p) {
    uint32_t a;
    asm("{ .reg .u64 t; cvta.to.shared.u64 t, %1; cvt.u32.u64 %0, t; }" : "=r"(a) : "l"(p));
    return a;
}
__device__ __forceinline__ void cp16(uint32_t s, const void* g) {
    asm volatile("cp.async.cg.shared.global [%0], [%1], 16;" :: "r"(s), "l"(g) : "memory");
}
#define CP_COMMIT() asm volatile("cp.async.commit_group;" ::: "memory")
#define CP_WAIT(n)  asm volatile("cp.async.wait_group %0;" :: "n"(n) : "memory")

__device__ __forceinline__ void ldm4(uint32_t r[4], uint32_t a) {
    asm volatile("ldmatrix.sync.aligned.m8n8.x4.shared.b16 {%0,%1,%2,%3}, [%4];"
                 : "=r"(r[0]), "=r"(r[1]), "=r"(r[2]), "=r"(r[3]) : "r"(a));
}
__device__ __forceinline__ void mma16816(float c[4], const uint32_t a[4], const uint32_t b[2]) {
    asm volatile("mma.sync.aligned.m16n8k16.row.col.f32.bf16.bf16.f32 "
                 "{%0,%1,%2,%3}, {%4,%5,%6,%7}, {%8,%9}, {%0,%1,%2,%3};"
                 : "+f"(c[0]), "+f"(c[1]), "+f"(c[2]), "+f"(c[3])
                 : "r"(a[0]), "r"(a[1]), "r"(a[2]), "r"(a[3]), "r"(b[0]), "r"(b[1]));
}

// ====================== split-bf16 HMMA GEMM ================================
// C[M,N] = (Ah+Al)[M,K] * (Bh+Bl)[N,K]^T   (all K-major bf16)
// CTA 128x128x32, 128 threads, 4 warps of 64x64, 2 CTAs/SM.
// XOR chunk swizzle on 64B rows: phys_chunk = c ^ ((row>>1)&3).
// Single-barrier multistage: loads for stage kt+2 issued right after the top
// barrier of iteration kt (into the slot freed at end of kt-1).
// EPI=0: fp32 C (attention GEMMs, z-batched via sA/sB/sC)
// EPI=1: bf16 hi/lo split C into Ch/Cl
// EPI=2: fused QKV projection — z=0 -> split(Ch,Cl), z=1 -> split(Ch2,Cl2),
//        z=2 -> fp32 C.  (sA=0, sB=D*D, outputs unbatched)
constexpr int ROW_B  = 64;            // 32 bf16, no pad (swizzled)
constexpr int COMP_B = 128 * ROW_B;   // 8192 B per component tile
constexpr int STG_B  = 4 * COMP_B;    // 32768 B (Ah,Al,Bh,Bl)
constexpr int NSTG   = 3;
constexpr int SMEM_SZ = NSTG * STG_B; // 98304 B -> 2 CTAs/SM

__device__ __forceinline__ void load_stage(uint32_t base,
    const bf16* __restrict__ ah, const bf16* __restrict__ al,
    const bf16* __restrict__ bh, const bf16* __restrict__ bl,
    int bm, int bn, int kt, int K, int tid)
{
    const int r  = tid >> 2;               // 0..31
    const int c  = tid & 3;                // logical 16B chunk in row
    const int kc = kt * 32 + c * 8;
    const int cp = c ^ ((r >> 1) & 3);     // swizzled chunk
#pragma unroll
    for (int g = 0; g < 4; g++) {          // row groups r, r+32, r+64, r+96
        const int row = r + g * 32;
        const uint32_t so = (uint32_t)row * ROW_B + cp * 16;
        const long ga = (long)(bm + row) * K + kc;
        const long gb = (long)(bn + row) * K + kc;
        cp16(base + so,              ah + ga);
        cp16(base + COMP_B + so,     al + ga);
        cp16(base + 2 * COMP_B + so, bh + gb);
        cp16(base + 3 * COMP_B + so, bl + gb);
    }
}

template <int EPI>
__global__ void __launch_bounds__(128, 2)
gemm_mma(const bf16* __restrict__ Agh, const bf16* __restrict__ Agl,
         const bf16* __restrict__ Bgh, const bf16* __restrict__ Bgl,
         float* __restrict__ C, bf16* __restrict__ Ch, bf16* __restrict__ Cl,
         bf16* __restrict__ Ch2, bf16* __restrict__ Cl2,
         int N, int K, long sA, long sB, long sC)
{
    extern __shared__ __align__(128) char smem[];
    const uint32_t sb = smem_u32(smem);
    const int tid = threadIdx.x, lane = tid & 31, warp = tid >> 5;
    const int wm = warp >> 1, wn = warp & 1;          // 2 x 2 warp grid, 64x64 tiles
    const int bm = blockIdx.y * 128, bn = blockIdx.x * 128, z = blockIdx.z;

    const bf16* Ah = Agh + (long)z * sA;
    const bf16* Al = Agl + (long)z * sA;
    const bf16* Bh = Bgh + (long)z * sB;
    const bf16* Bl = Bgl + (long)z * sB;

    const int nk = K >> 5;

    // ldmatrix per-thread address components (swizzle term invariant to +16 rows)
    const uint32_t aRow = (uint32_t)(wm * 64 + (lane & 15));
    const uint32_t aSw  = (aRow >> 1) & 3;
    const uint32_t aC0  = (uint32_t)((lane >> 4) & 1);
    const uint32_t bRow0 = (uint32_t)((lane & 7) | (((lane >> 4) & 1) << 3));
    const uint32_t bRow = (uint32_t)(wn * 64) + bRow0;
    const uint32_t bSw  = (bRow0 >> 1) & 3;
    const uint32_t bC0  = (uint32_t)((lane >> 3) & 1);

    float acc[4][8][4];
#pragma unroll
    for (int i = 0; i < 4; i++)
#pragma unroll
        for (int j = 0; j < 8; j++)
#pragma unroll
            for (int q = 0; q < 4; q++) acc[i][j][q] = 0.0f;

    // prologue: fill NSTG-1 stages
#pragma unroll
    for (int s = 0; s < NSTG - 1; s++) {
        load_stage(sb + s * STG_B, Ah, Al, Bh, Bl, bm, bn, s, K, tid);
        CP_COMMIT();
    }

    for (int kt = 0; kt < nk; kt++) {
        CP_WAIT(NSTG - 2);        // stage kt is resident
        __syncthreads();          // all warps done with stage kt-1's slot

        // issue loads for stage kt+2 into the just-freed slot, then compute kt
        const int nx = kt + NSTG - 1;
        if (nx < nk)
            load_stage(sb + (nx % NSTG) * STG_B, Ah, Al, Bh, Bl, bm, bn, nx, K, tid);
        CP_COMMIT();              // unconditional: exact group accounting

        const uint32_t st = sb + (kt % NSTG) * STG_B;
#pragma unroll
        for (int k16 = 0; k16 < 2; k16++) {
            const uint32_t aCk = ((uint32_t)(k16 * 2) + aC0) ^ aSw;
            const uint32_t bCk = ((uint32_t)(k16 * 2) + bC0) ^ bSw;
            const uint32_t aAddr = st + aRow * ROW_B + aCk * 16;
            const uint32_t bAddr = st + 2 * COMP_B + bRow * ROW_B + bCk * 16;
            uint32_t ah[4][4], al[4][4], bh[4][4], bl[4][4];
#pragma unroll
            for (int mi = 0; mi < 4; mi++) {
                ldm4(ah[mi], aAddr + mi * 16 * ROW_B);
                ldm4(al[mi], aAddr + COMP_B + mi * 16 * ROW_B);
            }
#pragma unroll
            for (int nb = 0; nb < 4; nb++) {
                ldm4(bh[nb], bAddr + nb * 16 * ROW_B);
                ldm4(bl[nb], bAddr + COMP_B + nb * 16 * ROW_B);
            }
#pragma unroll
            for (int mi = 0; mi < 4; mi++)
#pragma unroll
                for (int ni = 0; ni < 8; ni++) {
                    const uint32_t* bhp = &bh[ni >> 1][(ni & 1) * 2];
                    const uint32_t* blp = &bl[ni >> 1][(ni & 1) * 2];
                    mma16816(acc[mi][ni], ah[mi], bhp);  // hi*hi
                    mma16816(acc[mi][ni], ah[mi], blp);  // hi*lo
                    mma16816(acc[mi][ni], al[mi], bhp);  // lo*hi
                }
        }
    }

    // ---- epilogue ----
    bool wantF;
    long zoff;
    bf16* outH = Ch;
    bf16* outL = Cl;
    if (EPI == 0)      { wantF = true;  zoff = (long)z * sC; }
    else if (EPI == 1) { wantF = false; zoff = (long)z * sC; }
    else {             // fused projection
        zoff = 0;
        wantF = (z == 2);
        if (z == 1) { outH = Ch2; outL = Cl2; }
    }

    const int qr = lane >> 2, qc = (lane & 3) * 2;
#pragma unroll
    for (int mi = 0; mi < 4; mi++)
#pragma unroll
        for (int ni = 0; ni < 8; ni++) {
            const int m = bm + wm * 64 + mi * 16 + qr;
            const int n = bn + wn * 64 + ni * 8 + qc;
            const long o0 = zoff + (long)m * N + n;
            const long o1 = o0 + 8L * N;
            if (wantF) {
                *(float2*)(C + o0) = make_float2(acc[mi][ni][0], acc[mi][ni][1]);
                *(float2*)(C + o1) = make_float2(acc[mi][ni][2], acc[mi][ni][3]);
            } else {
                float x0 = acc[mi][ni][0], y0 = acc[mi][ni][1];
                float x1 = acc[mi][ni][2], y1 = acc[mi][ni][3];
                bf16 hx0 = __float2bfloat16(x0), hy0 = __float2bfloat16(y0);
                bf16 hx1 = __float2bfloat16(x1), hy1 = __float2bfloat16(y1);
                *(__nv_bfloat162*)(outH + o0) = __nv_bfloat162(hx0, hy0);
                *(__nv_bfloat162*)(outH + o1) = __nv_bfloat162(hx1, hy1);
                *(__nv_bfloat162*)(outL + o0) = __nv_bfloat162(
                    __float2bfloat16(x0 - __bfloat162float(hx0)),
                    __float2bfloat16(y0 - __bfloat162float(hy0)));
                *(__nv_bfloat162*)(outL + o1) = __nv_bfloat162(
                    __float2bfloat16(x1 - __bfloat162float(hx1)),
                    __float2bfloat16(y1 - __bfloat162float(hy1)));
            }
        }
}

// =========================== prep kernels ===================================
__global__ void split_f32(const float* __restrict__ in, bf16* __restrict__ oh,
                          bf16* __restrict__ ol)
{
    long i = ((long)blockIdx.x * 256 + threadIdx.x) * 4;
    float4 f = *(const float4*)(in + i);
    bf16 h0 = __float2bfloat16(f.x), h1 = __float2bfloat16(f.y);
    bf16 h2 = __float2bfloat16(f.z), h3 = __float2bfloat16(f.w);
    __nv_bfloat162* hp = (__nv_bfloat162*)(oh + i);
    __nv_bfloat162* lp = (__nv_bfloat162*)(ol + i);
    hp[0] = __nv_bfloat162(h0, h1);
    hp[1] = __nv_bfloat162(h2, h3);
    lp[0] = __nv_bfloat162(__float2bfloat16(f.x - __bfloat162float(h0)),
                           __float2bfloat16(f.y - __bfloat162float(h1)));
    lp[1] = __nv_bfloat162(__float2bfloat16(f.z - __bfloat162float(h2)),
                           __float2bfloat16(f.w - __bfloat162float(h3)));
}

// transpose [R,C] -> [C,R] with hi/lo bf16 split; z batches via strides
__global__ void tsplit(const float* __restrict__ in, bf16* __restrict__ oh,
                       bf16* __restrict__ ol, int R, int C, long sIn, long sOut)
{
    __shared__ float t[32][33];
    const int bx = blockIdx.x * 32, by = blockIdx.y * 32;
    const float* ip = in + (long)blockIdx.z * sIn;
    bf16* ohp = oh + (long)blockIdx.z * sOut;
    bf16* olp = ol + (long)blockIdx.z * sOut;
    const int tx = threadIdx.x;
#pragma unroll
    for (int i = threadIdx.y; i < 32; i += 8)
        t[i][tx] = ip[(long)(by + i) * C + bx + tx];
    __syncthreads();
#pragma unroll
    for (int i = threadIdx.y; i < 32; i += 8) {
        float f = t[tx][i];
        bf16 h = __float2bfloat16(f);
        long o = (long)(bx + i) * R + by + tx;
        ohp[o] = h;
        olp[o] = __float2bfloat16(f - __bfloat162float(h));
    }
}

// fused weight transpose+split: z selects Wq/Wk/Wv, output at z*D*D
__global__ void tsplitW(const float* __restrict__ w0, const float* __restrict__ w1,
                        const float* __restrict__ w2,
                        bf16* __restrict__ oh, bf16* __restrict__ ol)
{
    __shared__ float t[32][33];
    const int z = blockIdx.z;
    const float* ip = (z == 0) ? w0 : (z == 1) ? w1 : w2;
    const long zo = (long)z * D_DIM * D_DIM;
    const int bx = blockIdx.x * 32, by = blockIdx.y * 32;
    const int tx = threadIdx.x;
#pragma unroll
    for (int i = threadIdx.y; i < 32; i += 8)
        t[i][tx] = ip[(long)(by + i) * D_DIM + bx + tx];
    __syncthreads();
#pragma unroll
    for (int i = threadIdx.y; i < 32; i += 8) {
        float f = t[tx][i];
        bf16 h = __float2bfloat16(f);
        long o = zo + (long)(bx + i) * D_DIM + by + tx;
        oh[o] = h;
        ol[o] = __float2bfloat16(f - __bfloat162float(h));
    }
}

// ============================ softmax =======================================
__device__ __forceinline__ float warpMax(float v) {
#pragma unroll
    for (int o = 16; o; o >>= 1) v = fmaxf(v, __shfl_xor_sync(0xFFFFFFFFu, v, o));
    return v;
}
__device__ __forceinline__ float warpSum(float v) {
#pragma unroll
    for (int o = 16; o; o >>= 1) v += __shfl_xor_sync(0xFFFFFFFFu, v, o);
    return v;
}

struct alignas(8) bf16x4 { __nv_bfloat162 a, b; };

__global__ void softmax_rows(const float* __restrict__ Sc,
                             bf16* __restrict__ Wh, bf16* __restrict__ Wl)
{
    __shared__ float red[8];
    const long row = blockIdx.x;
    const float4* p4 = (const float4*)(Sc + row * (long)S_LEN);
    const int tid = threadIdx.x;
    const float scale = 0.03125f;  // 1/sqrt(1024)

    float4 va = p4[tid], vb = p4[tid + 256];
    float v[8] = {va.x, va.y, va.z, va.w, vb.x, vb.y, vb.z, vb.w};
    float mx = -3.402823e38f;
#pragma unroll
    for (int i = 0; i < 8; i++) { v[i] *= scale; mx = fmaxf(mx, v[i]); }
    mx = warpMax(mx);
    if ((tid & 31) == 0) red[tid >> 5] = mx;
    __syncthreads();
    if (tid < 32) {
        float m = (tid < 8) ? red[tid] : -3.402823e38f;
        m = warpMax(m);
        if (tid == 0) red[0] = m;
    }
    __syncthreads();
    mx = red[0];
    __syncthreads();

    float s = 0.0f;
#pragma unroll
    for (int i = 0; i < 8; i++) { v[i] = __expf(v[i] - mx); s += v[i]; }
    s = warpSum(s);
    if ((tid & 31) == 0) red[tid >> 5] = s;
    __syncthreads();
    if (tid < 32) {
        float t = (tid < 8) ? red[tid] : 0.0f;
        t = warpSum(t);
        if (tid == 0) red[0] = t;
    }
    __syncthreads();
    const float inv = 1.0f / red[0];

    bf16 h[8], l[8];
#pragma unroll
    for (int i = 0; i < 8; i++) {
        float w = v[i] * inv;
        h[i] = __float2bfloat16(w);
        l[i] = __float2bfloat16(w - __bfloat162float(h[i]));
    }
    bf16x4* wh4 = (bf16x4*)(Wh + row * (long)S_LEN);
    bf16x4* wl4 = (bf16x4*)(Wl + row * (long)S_LEN);
    wh4[tid]       = {__nv_bfloat162(h[0], h[1]), __nv_bfloat162(h[2], h[3])};
    wh4[tid + 256] = {__nv_bfloat162(h[4], h[5]), __nv_bfloat162(h[6], h[7])};
    wl4[tid]       = {__nv_bfloat162(l[0], l[1]), __nv_bfloat162(l[2], l[3])};
    wl4[tid + 256] = {__nv_bfloat162(l[4], l[5]), __nv_bfloat162(l[6], l[7])};
}

// ============================ host side =====================================
extern "C" void kernel_launch(void* const* d_in, const int* in_sizes, int n_in,
                              void* d_out, int out_size)
{
    const float* x  = (const float*)d_in[0];
    const float* Wq = (const float*)d_in[1];
    const float* Wk = (const float*)d_in[2];
    const float* Wv = (const float*)d_in[3];
    float* out = (float*)d_out;

    void *xh, *xl, *wth, *wtl, *qh, *ql, *kh, *kl, *v, *vth, *vtl, *sc, *wh, *wl;
    cudaGetSymbolAddress(&xh, g_xh);   cudaGetSymbolAddress(&xl, g_xl);
    cudaGetSymbolAddress(&wth, g_wth); cudaGetSymbolAddress(&wtl, g_wtl);
    cudaGetSymbolAddress(&qh, g_qh);   cudaGetSymbolAddress(&ql, g_ql);
    cudaGetSymbolAddress(&kh, g_kh);   cudaGetSymbolAddress(&kl, g_kl);
    cudaGetSymbolAddress(&v, g_v);
    cudaGetSymbolAddress(&vth, g_vth); cudaGetSymbolAddress(&vtl, g_vtl);
    cudaGetSymbolAddress(&sc, g_sc);
    cudaGetSymbolAddress(&wh, g_wh);   cudaGetSymbolAddress(&wl, g_wl);

    cudaFuncSetAttribute(gemm_mma<0>, cudaFuncAttributeMaxDynamicSharedMemorySize, SMEM_SZ);
    cudaFuncSetAttribute(gemm_mma<2>, cudaFuncAttributeMaxDynamicSharedMemorySize, SMEM_SZ);

    const long SD = (long)S_LEN * D_DIM, SS = (long)S_LEN * S_LEN;
    const long W1 = (long)D_DIM * D_DIM;

    // ---- data prep ----
    split_f32<<<(int)((long)MTOT * D_DIM / 1024), 256>>>(x, (bf16*)xh, (bf16*)xl);
    dim3 tb(32, 8);
    tsplitW<<<dim3(32, 32, 3), tb>>>(Wq, Wk, Wv, (bf16*)wth, (bf16*)wtl);

    // ---- fused QKV projection: z=0 -> Q split, z=1 -> K split, z=2 -> V fp32
    dim3 gp(D_DIM / 128, MTOT / 128, 3);
    gemm_mma<2><<<gp, 128, SMEM_SZ>>>((bf16*)xh, (bf16*)xl, (bf16*)wth, (bf16*)wtl,
        (float*)v, (bf16*)qh, (bf16*)ql, (bf16*)kh, (bf16*)kl,
        D_DIM, D_DIM, 0, W1, 0);

    // V -> V^T hi/lo per batch
    tsplit<<<dim3(D_DIM / 32, S_LEN / 32, BATCH), tb>>>(
        (const float*)v, (bf16*)vth, (bf16*)vtl, S_LEN, D_DIM, SD, SD);

    // scores = Q K^T per batch
    dim3 gs(S_LEN / 128, S_LEN / 128, BATCH);
    gemm_mma<0><<<gs, 128, SMEM_SZ>>>((bf16*)qh, (bf16*)ql, (bf16*)kh, (bf16*)kl,
        (float*)sc, nullptr, nullptr, nullptr, nullptr, S_LEN, D_DIM, SD, SD, SS);

    softmax_rows<<<BATCH * S_LEN, 256>>>((const float*)sc, (bf16*)wh, (bf16*)wl);

    // out = softmaxW * V  (B = V^T, K-major)
    dim3 ga(D_DIM / 128, S_LEN / 128, BATCH);
    gemm_mma<0><<<ga, 128, SMEM_SZ>>>((bf16*)wh, (bf16*)wl, (bf16*)vth, (bf16*)vtl,
        out, nullptr, nullptr, nullptr, nullptr, D_DIM, S_LEN, SS, SD, SD);
}